// round 1
// baseline (speedup 1.0000x reference)
#include <cuda_runtime.h>
#include <cuda_bf16.h>

#define PLANE_RES 1024

__global__ __launch_bounds__(256) void triplane_kernel(
    const float* __restrict__ positions,
    const float* __restrict__ table,
    float* __restrict__ out,
    int B)
{
    int b = blockIdx.x * blockDim.x + threadIdx.x;
    if (b >= B) return;

    float pos[3];
    pos[0] = positions[3 * b + 0];
    pos[1] = positions[3 * b + 1];
    pos[2] = positions[3 * b + 2];

    const float2* __restrict__ tab = (const float2*)table;

    const float scales[4] = {128.0f, 256.0f, 512.0f, 1024.0f};
    const int   facs[4]   = {8, 4, 2, 1};

    float* o = out + (size_t)b * 32;

    #pragma unroll
    for (int L = 0; L < 4; L++) {
        const float s = scales[L] - 1.0f;
        const int fac = facs[L];

        int   g[3];
        float fr[3];
        #pragma unroll
        for (int d = 0; d < 3; d++) {
            float x  = fmaf(pos[d], s, 0.5f);
            float gf = floorf(x);
            g[d]  = (int)gf;
            fr[d] = x - gf;
        }

        float acc[3][2];
        #pragma unroll
        for (int pl = 0; pl < 3; pl++) {
            const int a0 = pl;
            const int a1 = (pl + 1) % 3;   // c0=[0,1,2], c1=[1,2,0]
            const float f0 = fr[a0];
            const float f1 = fr[a1];
            const int g0 = g[a0];
            const int g1 = g[a1];

            int i0 = min(g0 * fac,        PLANE_RES - 1);
            int i1 = min((g0 + 1) * fac,  PLANE_RES - 1);
            int j0 = min(g1 * fac,        PLANE_RES - 1);
            int j1 = min((g1 + 1) * fac,  PLANE_RES - 1);

            const float2* __restrict__ base = tab + (size_t)pl * (PLANE_RES * PLANE_RES);
            float2 v00 = __ldg(base + (i0 + j0 * PLANE_RES));
            float2 v10 = __ldg(base + (i1 + j0 * PLANE_RES));
            float2 v01 = __ldg(base + (i0 + j1 * PLANE_RES));
            float2 v11 = __ldg(base + (i1 + j1 * PLANE_RES));

            const float w00 = (1.0f - f0) * (1.0f - f1);
            const float w10 = f0 * (1.0f - f1);
            const float w01 = (1.0f - f0) * f1;
            const float w11 = f0 * f1;

            acc[pl][0] = w00 * v00.x + w10 * v10.x + w01 * v01.x + w11 * v11.x;
            acc[pl][1] = w00 * v00.y + w10 * v10.y + w01 * v01.y + w11 * v11.y;
        }

        const float pr0 = acc[0][0] * acc[1][0] * acc[2][0];
        const float pr1 = acc[0][1] * acc[1][1] * acc[2][1];

        float4* ov = (float4*)(o + L * 8);
        ov[0] = make_float4(acc[0][0], acc[0][1], acc[1][0], acc[1][1]);
        ov[1] = make_float4(acc[2][0], acc[2][1], pr0, pr1);
    }
}

extern "C" void kernel_launch(void* const* d_in, const int* in_sizes, int n_in,
                              void* d_out, int out_size) {
    const float* positions = (const float*)d_in[0];
    const float* table     = (const float*)d_in[1];
    float*       out       = (float*)d_out;

    int B = in_sizes[0] / 3;
    int threads = 256;
    int blocks  = (B + threads - 1) / threads;
    triplane_kernel<<<blocks, threads>>>(positions, table, out, B);
}

// round 2
// speedup vs baseline: 1.3438x; 1.3438x over previous
#include <cuda_runtime.h>
#include <cuda_bf16.h>

#define NPAIR_TOTAL 4183680
// Level layout in g_pairs (float4 entries):
//   lvl L: scale s in {128,256,512,1024}, fac = 1024/s
//   entries: 3 planes x (s+1) rows x s cols
//   offsets: L0=0, L1=49536, L2=246912, L3=1034880
__device__ float4 g_pairs[NPAIR_TOTAL];

__global__ __launch_bounds__(256) void build_pairs_kernel(const float* __restrict__ table)
{
    int t = blockIdx.x * blockDim.x + threadIdx.x;
    if (t >= NPAIR_TOTAL) return;

    int s, off, fac;
    if (t < 49536)        { s = 128;  off = 0;       fac = 8; }
    else if (t < 246912)  { s = 256;  off = 49536;   fac = 4; }
    else if (t < 1034880) { s = 512;  off = 246912;  fac = 2; }
    else                  { s = 1024; off = 1034880; fac = 1; }

    int r = t - off;
    int per_plane = (s + 1) * s;
    int pl = r / per_plane;
    int r2 = r - pl * per_plane;
    int j = r2 / s;
    int i = r2 - j * s;

    int row = min(j * fac, 1023);
    int i0  = min(i * fac, 1023);
    int i1  = min((i + 1) * fac, 1023);

    const float2* __restrict__ tab = (const float2*)table + (size_t)pl * (1024 * 1024);
    float2 a = tab[row * 1024 + i0];
    float2 b = tab[row * 1024 + i1];
    g_pairs[t] = make_float4(a.x, a.y, b.x, b.y);
}

__global__ __launch_bounds__(256) void triplane_kernel(
    const float* __restrict__ positions,
    float* __restrict__ out,
    int B)
{
    int b = blockIdx.x * blockDim.x + threadIdx.x;
    if (b >= B) return;

    float pos[3];
    pos[0] = positions[3 * b + 0];
    pos[1] = positions[3 * b + 1];
    pos[2] = positions[3 * b + 2];

    const int   S[4]   = {128, 256, 512, 1024};
    const int   OFF[4] = {0, 49536, 246912, 1034880};

    float* o = out + (size_t)b * 32;

    #pragma unroll
    for (int L = 0; L < 4; L++) {
        const int s = S[L];
        const float sm1 = (float)s - 1.0f;
        const int lvl_off = OFF[L];

        int   g[3];
        float fr[3];
        #pragma unroll
        for (int d = 0; d < 3; d++) {
            float x  = fmaf(pos[d], sm1, 0.5f);
            float gf = floorf(x);
            g[d]  = (int)gf;
            fr[d] = x - gf;
        }

        float acc[3][2];
        #pragma unroll
        for (int pl = 0; pl < 3; pl++) {
            const int a0 = pl;
            const int a1 = (pl + 1) % 3;   // c0=[0,1,2], c1=[1,2,0]
            const float f0 = fr[a0];
            const float f1 = fr[a1];
            const int i  = g[a0];          // 0..s-1 (compact col)
            const int j0 = g[a1];          // 0..s-1 ; j0+1 <= s (compact row)

            const int base = lvl_off + (pl * (s + 1) + j0) * s + i;
            float4 r0 = __ldg(&g_pairs[base]);       // row j0:   (v00, v10)
            float4 r1 = __ldg(&g_pairs[base + s]);   // row j0+1: (v01, v11)

            // bilinear: (1-f1)*[(1-f0)*v00 + f0*v10] + f1*[(1-f0)*v01 + f0*v11]
            const float w0 = 1.0f - f0;
            float l0x = w0 * r0.x + f0 * r0.z;
            float l0y = w0 * r0.y + f0 * r0.w;
            float l1x = w0 * r1.x + f0 * r1.z;
            float l1y = w0 * r1.y + f0 * r1.w;

            const float w1 = 1.0f - f1;
            acc[pl][0] = w1 * l0x + f1 * l1x;
            acc[pl][1] = w1 * l0y + f1 * l1y;
        }

        const float pr0 = acc[0][0] * acc[1][0] * acc[2][0];
        const float pr1 = acc[0][1] * acc[1][1] * acc[2][1];

        float4* ov = (float4*)(o + L * 8);
        ov[0] = make_float4(acc[0][0], acc[0][1], acc[1][0], acc[1][1]);
        ov[1] = make_float4(acc[2][0], acc[2][1], pr0, pr1);
    }
}

extern "C" void kernel_launch(void* const* d_in, const int* in_sizes, int n_in,
                              void* d_out, int out_size) {
    const float* positions = (const float*)d_in[0];
    const float* table     = (const float*)d_in[1];
    float*       out       = (float*)d_out;

    int B = in_sizes[0] / 3;

    {
        int threads = 256;
        int blocks = (NPAIR_TOTAL + threads - 1) / threads;
        build_pairs_kernel<<<blocks, threads>>>(table);
    }
    {
        int threads = 256;
        int blocks  = (B + threads - 1) / threads;
        triplane_kernel<<<blocks, threads>>>(positions, out, B);
    }
}